// round 2
// baseline (speedup 1.0000x reference)
#include <cuda_runtime.h>

#define NWIN 4096
#define NTOK 64
#define DIM 192
#define HEADS 6
#define HD 32

// Shared memory layout (floats):
//   [0, 12288)        sx  : x tile [64][192]   -- reused as sout (attn output) in phases B/C
//   [12288, 49152)    sqkv: [3][6][64][32]     -- q,k,v per head, d-contiguous
//   [49152, 55488)    sR  : union region (6336 floats = 25344 B)
//        phase A/C: swcT [192][33] transposed weight chunk (32 cols)
//        phase B  : sattn [64][65] probs  +  sbias [225*6] bias table copy @ offset 4160
#define SM_FLOATS 55488

__global__ void __launch_bounds__(256, 1) msa_fused_kernel(
    const float* __restrict__ x,
    const float* __restrict__ qkv_w,
    const float* __restrict__ qkv_b,
    const float* __restrict__ proj_w,
    const float* __restrict__ proj_b,
    const float* __restrict__ bias_table,
    const int*   __restrict__ rel_index,
    float* __restrict__ out)
{
    extern __shared__ float sm[];
    float* sx    = sm;            // 12288 floats (also attn-output buffer)
    float* sqkv  = sm + 12288;    // 36864 floats
    float* sR    = sm + 49152;    // 6336 floats
    float* swcT  = sR;            // [192][33]
    float* sattn = sR;            // [64][65]
    float* sbias = sR + 4160;     // [225*6]

    const int tid  = threadIdx.x;
    const int b    = blockIdx.x;
    const int warp = tid >> 5;
    const int lane = tid & 31;
    const int n0   = warp * 8;    // 8 token rows per warp in GEMM phases

    // ---------------- load x tile (coalesced float4) ----------------
    {
        const float4* xg = reinterpret_cast<const float4*>(x + (size_t)b * (NTOK * DIM));
        float4* xs = reinterpret_cast<float4*>(sx);
        #pragma unroll
        for (int r = 0; r < 12; r++) xs[tid + r * 256] = xg[tid + r * 256];
    }

    // ---------------- Phase A: qkv = x @ qkv_w^T + qkv_b ----------------
    // 18 chunks of 32 output columns; chunk mc covers m = mc*32..+31 which is
    // exactly one (t,h) pair with d = lane.
    for (int mc = 0; mc < 18; mc++) {
        __syncthreads();  // protect swcT reuse (and x-load on first iter)
        // stage weight chunk transposed: swcT[c][m_local], stride 33 (conflict-free)
        {
            const float4* wg = reinterpret_cast<const float4*>(qkv_w + (size_t)mc * 32 * DIM);
            #pragma unroll
            for (int r = 0; r < 6; r++) {
                int idx = tid + r * 256;          // 0..1535
                int ml = idx / 48;                // 0..31 (row within chunk)
                int cq = idx % 48;                // float4 index along c
                float4 v = wg[ml * 48 + cq];
                swcT[(cq * 4 + 0) * 33 + ml] = v.x;
                swcT[(cq * 4 + 1) * 33 + ml] = v.y;
                swcT[(cq * 4 + 2) * 33 + ml] = v.z;
                swcT[(cq * 4 + 3) * 33 + ml] = v.w;
            }
        }
        __syncthreads();

        const int m = mc * 32 + lane;
        float acc[8];
        {
            const float bm = qkv_b[m];
            #pragma unroll
            for (int i = 0; i < 8; i++) acc[i] = bm;
        }
        #pragma unroll 4
        for (int c4 = 0; c4 < DIM; c4 += 4) {
            const float w0 = swcT[(c4 + 0) * 33 + lane];
            const float w1 = swcT[(c4 + 1) * 33 + lane];
            const float w2 = swcT[(c4 + 2) * 33 + lane];
            const float w3 = swcT[(c4 + 3) * 33 + lane];
            #pragma unroll
            for (int i = 0; i < 8; i++) {
                const float4 xv = *reinterpret_cast<const float4*>(&sx[(n0 + i) * DIM + c4]);
                acc[i] = fmaf(xv.x, w0, acc[i]);
                acc[i] = fmaf(xv.y, w1, acc[i]);
                acc[i] = fmaf(xv.z, w2, acc[i]);
                acc[i] = fmaf(xv.w, w3, acc[i]);
            }
        }
        // store to sqkv[(t*6+h)=mc][n][d=lane]  (32-float coalesced per warp)
        float* dst = sqkv + mc * 2048 + lane;
        #pragma unroll
        for (int i = 0; i < 8; i++) dst[(n0 + i) * 32] = acc[i];
    }

    __syncthreads();

    // stage bias table copy into sR tail (past the sattn area)
    for (int i = tid; i < 225 * HEADS; i += 256) sbias[i] = bias_table[i];

    // ---------------- Phase B: attention per head ----------------
    const float scaleA = 0.17677669529663687f;  // 1/sqrt(32)
    const int qi = tid >> 2;     // token row 0..63
    const int jq = tid & 3;      // quarter of the 64 keys / output dims

    for (int h = 0; h < HEADS; h++) {
        const float* sq = sqkv + h * 2048;
        const float* sk = sqkv + (HEADS + h) * 2048;
        const float* sv = sqkv + (2 * HEADS + h) * 2048;

        __syncthreads();  // sattn consumed by previous head (and sbias ready on h=0)

        // q row into registers (broadcast within 4-lane groups)
        float4 qv[8];
        #pragma unroll
        for (int d4 = 0; d4 < 8; d4++)
            qv[d4] = *reinterpret_cast<const float4*>(&sq[qi * 32 + d4 * 4]);

        // scores for j = jq*16 .. jq*16+15
        float s[16];
        #pragma unroll
        for (int jj = 0; jj < 16; jj++) {
            const int j = jq * 16 + jj;
            const float4* kr = reinterpret_cast<const float4*>(&sk[j * 32]);
            float a = 0.f;
            #pragma unroll
            for (int d4 = 0; d4 < 8; d4++) {
                const float4 kv = kr[d4];
                a = fmaf(qv[d4].x, kv.x, a);
                a = fmaf(qv[d4].y, kv.y, a);
                a = fmaf(qv[d4].z, kv.z, a);
                a = fmaf(qv[d4].w, kv.w, a);
            }
            const int ridx = rel_index[qi * 64 + j];
            s[jj] = fmaf(a, scaleA, sbias[ridx * HEADS + h]);
        }

        // softmax across row: 16 local + 4 lanes (lanes differ in low 2 bits)
        float mx = s[0];
        #pragma unroll
        for (int jj = 1; jj < 16; jj++) mx = fmaxf(mx, s[jj]);
        mx = fmaxf(mx, __shfl_xor_sync(0xffffffffu, mx, 1));
        mx = fmaxf(mx, __shfl_xor_sync(0xffffffffu, mx, 2));
        float sum = 0.f;
        #pragma unroll
        for (int jj = 0; jj < 16; jj++) { s[jj] = __expf(s[jj] - mx); sum += s[jj]; }
        sum += __shfl_xor_sync(0xffffffffu, sum, 1);
        sum += __shfl_xor_sync(0xffffffffu, sum, 2);
        const float inv = 1.0f / sum;
        #pragma unroll
        for (int jj = 0; jj < 16; jj++)
            sattn[qi * 65 + jq * 16 + jj] = s[jj] * inv;

        __syncthreads();

        // PV: out[qi][d0..d0+7] = sum_j p[qi][j] * v[j][d]
        const int d0 = jq * 8;
        float o[8];
        #pragma unroll
        for (int k = 0; k < 8; k++) o[k] = 0.f;
        #pragma unroll 4
        for (int j = 0; j < 64; j++) {
            const float p = sattn[qi * 65 + j];
            const float4 v0 = *reinterpret_cast<const float4*>(&sv[j * 32 + d0]);
            const float4 v1 = *reinterpret_cast<const float4*>(&sv[j * 32 + d0 + 4]);
            o[0] = fmaf(p, v0.x, o[0]);
            o[1] = fmaf(p, v0.y, o[1]);
            o[2] = fmaf(p, v0.z, o[2]);
            o[3] = fmaf(p, v0.w, o[3]);
            o[4] = fmaf(p, v1.x, o[4]);
            o[5] = fmaf(p, v1.y, o[5]);
            o[6] = fmaf(p, v1.z, o[6]);
            o[7] = fmaf(p, v1.w, o[7]);
        }
        // write head output into sout (= sx) at columns h*32+d0..+7
        float* op = &sx[qi * DIM + h * 32 + d0];
        *reinterpret_cast<float4*>(op)     = make_float4(o[0], o[1], o[2], o[3]);
        *reinterpret_cast<float4*>(op + 4) = make_float4(o[4], o[5], o[6], o[7]);
    }

    // ---------------- Phase C: out = sout @ proj_w^T + proj_b ----------------
    const float4* pwg4 = reinterpret_cast<const float4*>(proj_w);
    for (int ec = 0; ec < 6; ec++) {
        __syncthreads();  // sattn reads / sout writes done before swcT overwrite
        #pragma unroll
        for (int r = 0; r < 6; r++) {
            int idx = tid + r * 256;
            int el = idx / 48;
            int cq = idx % 48;
            float4 v = pwg4[(ec * 32 + el) * 48 + cq];
            swcT[(cq * 4 + 0) * 33 + el] = v.x;
            swcT[(cq * 4 + 1) * 33 + el] = v.y;
            swcT[(cq * 4 + 2) * 33 + el] = v.z;
            swcT[(cq * 4 + 3) * 33 + el] = v.w;
        }
        __syncthreads();

        const int e = ec * 32 + lane;
        float acc[8];
        {
            const float be = proj_b[e];
            #pragma unroll
            for (int i = 0; i < 8; i++) acc[i] = be;
        }
        #pragma unroll 4
        for (int c4 = 0; c4 < DIM; c4 += 4) {
            const float w0 = swcT[(c4 + 0) * 33 + lane];
            const float w1 = swcT[(c4 + 1) * 33 + lane];
            const float w2 = swcT[(c4 + 2) * 33 + lane];
            const float w3 = swcT[(c4 + 3) * 33 + lane];
            #pragma unroll
            for (int i = 0; i < 8; i++) {
                const float4 xv = *reinterpret_cast<const float4*>(&sx[(n0 + i) * DIM + c4]);
                acc[i] = fmaf(xv.x, w0, acc[i]);
                acc[i] = fmaf(xv.y, w1, acc[i]);
                acc[i] = fmaf(xv.z, w2, acc[i]);
                acc[i] = fmaf(xv.w, w3, acc[i]);
            }
        }
        // coalesced 128B stores: lanes cover 32 consecutive output columns
        float* og = out + (size_t)b * (NTOK * DIM) + ec * 32 + lane;
        #pragma unroll
        for (int i = 0; i < 8; i++) og[(n0 + i) * DIM] = acc[i];
    }
}

extern "C" void kernel_launch(void* const* d_in, const int* in_sizes, int n_in,
                              void* d_out, int out_size) {
    const float* x          = (const float*)d_in[0];
    const float* qkv_w      = (const float*)d_in[1];
    const float* qkv_b      = (const float*)d_in[2];
    const float* proj_w     = (const float*)d_in[3];
    const float* proj_b     = (const float*)d_in[4];
    const float* bias_table = (const float*)d_in[5];
    const int*   rel_index  = (const int*)d_in[6];
    float* out = (float*)d_out;

    const size_t smem = SM_FLOATS * sizeof(float);  // 221952 B
    cudaFuncSetAttribute(msa_fused_kernel,
                         cudaFuncAttributeMaxDynamicSharedMemorySize, (int)smem);
    msa_fused_kernel<<<NWIN, 256, smem>>>(x, qkv_w, qkv_b, proj_w, proj_b,
                                          bias_table, rel_index, out);
}

// round 3
// speedup vs baseline: 1.0007x; 1.0007x over previous
#include <cuda_runtime.h>

#define NWIN 4096
#define NTOK 64
#define DIM 192
#define HEADS 6
#define HD 32

// Shared memory layout (floats):
//   [0, 12288)        sx  : x tile [64][192]   -- reused as sout (attn output) in phases B/C
//   [12288, 49152)    sqkv: [3][6][64][32]     -- q,k,v per head, d-contiguous
//   [49152, 55488)    sR  : union region (6336 floats = 25344 B)
//        phase A/C: swcT [192][33] transposed weight chunk (32 cols)
//        phase B  : sattn [64][65] probs  +  sbias [225*6] bias table copy @ offset 4160
#define SM_FLOATS 55488

__global__ void __launch_bounds__(256, 1) msa_fused_kernel(
    const float* __restrict__ x,
    const float* __restrict__ qkv_w,
    const float* __restrict__ qkv_b,
    const float* __restrict__ proj_w,
    const float* __restrict__ proj_b,
    const float* __restrict__ bias_table,
    const int*   __restrict__ rel_index,
    float* __restrict__ out)
{
    extern __shared__ float sm[];
    float* sx    = sm;            // 12288 floats (also attn-output buffer)
    float* sqkv  = sm + 12288;    // 36864 floats
    float* sR    = sm + 49152;    // 6336 floats
    float* swcT  = sR;            // [192][33]
    float* sattn = sR;            // [64][65]
    float* sbias = sR + 4160;     // [225*6]

    const int tid  = threadIdx.x;
    const int b    = blockIdx.x;
    const int warp = tid >> 5;
    const int lane = tid & 31;
    const int n0   = warp * 8;    // 8 token rows per warp in GEMM phases

    // ---------------- load x tile (coalesced float4) ----------------
    {
        const float4* xg = reinterpret_cast<const float4*>(x + (size_t)b * (NTOK * DIM));
        float4* xs = reinterpret_cast<float4*>(sx);
        #pragma unroll
        for (int r = 0; r < 12; r++) xs[tid + r * 256] = xg[tid + r * 256];
    }

    // ---------------- Phase A: qkv = x @ qkv_w^T + qkv_b ----------------
    // 18 chunks of 32 output columns; chunk mc covers m = mc*32..+31 which is
    // exactly one (t,h) pair with d = lane.
    for (int mc = 0; mc < 18; mc++) {
        __syncthreads();  // protect swcT reuse (and x-load on first iter)
        // stage weight chunk transposed: swcT[c][m_local], stride 33 (conflict-free)
        {
            const float4* wg = reinterpret_cast<const float4*>(qkv_w + (size_t)mc * 32 * DIM);
            #pragma unroll
            for (int r = 0; r < 6; r++) {
                int idx = tid + r * 256;          // 0..1535
                int ml = idx / 48;                // 0..31 (row within chunk)
                int cq = idx % 48;                // float4 index along c
                float4 v = wg[ml * 48 + cq];
                swcT[(cq * 4 + 0) * 33 + ml] = v.x;
                swcT[(cq * 4 + 1) * 33 + ml] = v.y;
                swcT[(cq * 4 + 2) * 33 + ml] = v.z;
                swcT[(cq * 4 + 3) * 33 + ml] = v.w;
            }
        }
        __syncthreads();

        const int m = mc * 32 + lane;
        float acc[8];
        {
            const float bm = qkv_b[m];
            #pragma unroll
            for (int i = 0; i < 8; i++) acc[i] = bm;
        }
        #pragma unroll 4
        for (int c4 = 0; c4 < DIM; c4 += 4) {
            const float w0 = swcT[(c4 + 0) * 33 + lane];
            const float w1 = swcT[(c4 + 1) * 33 + lane];
            const float w2 = swcT[(c4 + 2) * 33 + lane];
            const float w3 = swcT[(c4 + 3) * 33 + lane];
            #pragma unroll
            for (int i = 0; i < 8; i++) {
                const float4 xv = *reinterpret_cast<const float4*>(&sx[(n0 + i) * DIM + c4]);
                acc[i] = fmaf(xv.x, w0, acc[i]);
                acc[i] = fmaf(xv.y, w1, acc[i]);
                acc[i] = fmaf(xv.z, w2, acc[i]);
                acc[i] = fmaf(xv.w, w3, acc[i]);
            }
        }
        // store to sqkv[(t*6+h)=mc][n][d=lane]  (32-float coalesced per warp)
        float* dst = sqkv + mc * 2048 + lane;
        #pragma unroll
        for (int i = 0; i < 8; i++) dst[(n0 + i) * 32] = acc[i];
    }

    __syncthreads();

    // stage bias table copy into sR tail (past the sattn area)
    for (int i = tid; i < 225 * HEADS; i += 256) sbias[i] = bias_table[i];

    // ---------------- Phase B: attention per head ----------------
    const float scaleA = 0.17677669529663687f;  // 1/sqrt(32)
    const int qi = tid >> 2;     // token row 0..63
    const int jq = tid & 3;      // quarter of the 64 keys / output dims

    for (int h = 0; h < HEADS; h++) {
        const float* sq = sqkv + h * 2048;
        const float* sk = sqkv + (HEADS + h) * 2048;
        const float* sv = sqkv + (2 * HEADS + h) * 2048;

        __syncthreads();  // sattn consumed by previous head (and sbias ready on h=0)

        // q row into registers (broadcast within 4-lane groups)
        float4 qv[8];
        #pragma unroll
        for (int d4 = 0; d4 < 8; d4++)
            qv[d4] = *reinterpret_cast<const float4*>(&sq[qi * 32 + d4 * 4]);

        // scores for j = jq*16 .. jq*16+15
        float s[16];
        #pragma unroll
        for (int jj = 0; jj < 16; jj++) {
            const int j = jq * 16 + jj;
            const float4* kr = reinterpret_cast<const float4*>(&sk[j * 32]);
            float a = 0.f;
            #pragma unroll
            for (int d4 = 0; d4 < 8; d4++) {
                const float4 kv = kr[d4];
                a = fmaf(qv[d4].x, kv.x, a);
                a = fmaf(qv[d4].y, kv.y, a);
                a = fmaf(qv[d4].z, kv.z, a);
                a = fmaf(qv[d4].w, kv.w, a);
            }
            const int ridx = rel_index[qi * 64 + j];
            s[jj] = fmaf(a, scaleA, sbias[ridx * HEADS + h]);
        }

        // softmax across row: 16 local + 4 lanes (lanes differ in low 2 bits)
        float mx = s[0];
        #pragma unroll
        for (int jj = 1; jj < 16; jj++) mx = fmaxf(mx, s[jj]);
        mx = fmaxf(mx, __shfl_xor_sync(0xffffffffu, mx, 1));
        mx = fmaxf(mx, __shfl_xor_sync(0xffffffffu, mx, 2));
        float sum = 0.f;
        #pragma unroll
        for (int jj = 0; jj < 16; jj++) { s[jj] = __expf(s[jj] - mx); sum += s[jj]; }
        sum += __shfl_xor_sync(0xffffffffu, sum, 1);
        sum += __shfl_xor_sync(0xffffffffu, sum, 2);
        const float inv = 1.0f / sum;
        #pragma unroll
        for (int jj = 0; jj < 16; jj++)
            sattn[qi * 65 + jq * 16 + jj] = s[jj] * inv;

        __syncthreads();

        // PV: out[qi][d0..d0+7] = sum_j p[qi][j] * v[j][d]
        const int d0 = jq * 8;
        float o[8];
        #pragma unroll
        for (int k = 0; k < 8; k++) o[k] = 0.f;
        #pragma unroll 4
        for (int j = 0; j < 64; j++) {
            const float p = sattn[qi * 65 + j];
            const float4 v0 = *reinterpret_cast<const float4*>(&sv[j * 32 + d0]);
            const float4 v1 = *reinterpret_cast<const float4*>(&sv[j * 32 + d0 + 4]);
            o[0] = fmaf(p, v0.x, o[0]);
            o[1] = fmaf(p, v0.y, o[1]);
            o[2] = fmaf(p, v0.z, o[2]);
            o[3] = fmaf(p, v0.w, o[3]);
            o[4] = fmaf(p, v1.x, o[4]);
            o[5] = fmaf(p, v1.y, o[5]);
            o[6] = fmaf(p, v1.z, o[6]);
            o[7] = fmaf(p, v1.w, o[7]);
        }
        // write head output into sout (= sx) at columns h*32+d0..+7
        float* op = &sx[qi * DIM + h * 32 + d0];
        *reinterpret_cast<float4*>(op)     = make_float4(o[0], o[1], o[2], o[3]);
        *reinterpret_cast<float4*>(op + 4) = make_float4(o[4], o[5], o[6], o[7]);
    }

    // ---------------- Phase C: out = sout @ proj_w^T + proj_b ----------------
    const float4* pwg4 = reinterpret_cast<const float4*>(proj_w);
    for (int ec = 0; ec < 6; ec++) {
        __syncthreads();  // sattn reads / sout writes done before swcT overwrite
        #pragma unroll
        for (int r = 0; r < 6; r++) {
            int idx = tid + r * 256;
            int el = idx / 48;
            int cq = idx % 48;
            float4 v = pwg4[(ec * 32 + el) * 48 + cq];
            swcT[(cq * 4 + 0) * 33 + el] = v.x;
            swcT[(cq * 4 + 1) * 33 + el] = v.y;
            swcT[(cq * 4 + 2) * 33 + el] = v.z;
            swcT[(cq * 4 + 3) * 33 + el] = v.w;
        }
        __syncthreads();

        const int e = ec * 32 + lane;
        float acc[8];
        {
            const float be = proj_b[e];
            #pragma unroll
            for (int i = 0; i < 8; i++) acc[i] = be;
        }
        #pragma unroll 4
        for (int c4 = 0; c4 < DIM; c4 += 4) {
            const float w0 = swcT[(c4 + 0) * 33 + lane];
            const float w1 = swcT[(c4 + 1) * 33 + lane];
            const float w2 = swcT[(c4 + 2) * 33 + lane];
            const float w3 = swcT[(c4 + 3) * 33 + lane];
            #pragma unroll
            for (int i = 0; i < 8; i++) {
                const float4 xv = *reinterpret_cast<const float4*>(&sx[(n0 + i) * DIM + c4]);
                acc[i] = fmaf(xv.x, w0, acc[i]);
                acc[i] = fmaf(xv.y, w1, acc[i]);
                acc[i] = fmaf(xv.z, w2, acc[i]);
                acc[i] = fmaf(xv.w, w3, acc[i]);
            }
        }
        // coalesced 128B stores: lanes cover 32 consecutive output columns
        float* og = out + (size_t)b * (NTOK * DIM) + ec * 32 + lane;
        #pragma unroll
        for (int i = 0; i < 8; i++) og[(n0 + i) * DIM] = acc[i];
    }
}

extern "C" void kernel_launch(void* const* d_in, const int* in_sizes, int n_in,
                              void* d_out, int out_size) {
    const float* x          = (const float*)d_in[0];
    const float* qkv_w      = (const float*)d_in[1];
    const float* qkv_b      = (const float*)d_in[2];
    const float* proj_w     = (const float*)d_in[3];
    const float* proj_b     = (const float*)d_in[4];
    const float* bias_table = (const float*)d_in[5];
    const int*   rel_index  = (const int*)d_in[6];
    float* out = (float*)d_out;

    const size_t smem = SM_FLOATS * sizeof(float);  // 221952 B
    cudaFuncSetAttribute(msa_fused_kernel,
                         cudaFuncAttributeMaxDynamicSharedMemorySize, (int)smem);
    msa_fused_kernel<<<NWIN, 256, smem>>>(x, qkv_w, qkv_b, proj_w, proj_b,
                                          bias_table, rel_index, out);
}